// round 11
// baseline (speedup 1.0000x reference)
#include <cuda_runtime.h>
#include <math.h>

#define S 192
#define HD 64
#define NHEAD 8
#define SS (S*S)

// Output layout (concatenated flattened tuple, reference return order):
#define Z_OFF      0u
#define SCORE_OFF  98304u
#define VG_OFF     56721408u
#define M_OFF      75595776u

// z1 -> z2 handoff
__device__ float g_U[NHEAD * S * HD];   // [n][t][h]
__device__ float g_Cc[NHEAD * S];       // sum_s exp(0.125 kk[s,t])
__device__ float g_lk[NHEAD * S];       // log(max_s exp(0.125 kk[s,t]))
__device__ int   d_done[NHEAD];         // z1 completion counters (self-resetting)
__device__ int   d_cons[NHEAD];         // z2 consumption counters (self-resetting)

// block role ranges
#define Z1_BASE    0
#define Z2_BASE    96
#define VG_BASE    192
#define SC_BASE    1344
#define VG_BLOCKS  1152   // 8 * 12 * 12
#define SC_BLOCKS  6144   // 8 * 4 * 192
#define TOTAL_BLOCKS 7488

// dynamic smem: max over roles = z2's 5856 floats
#define SMEM_FLOATS 5856

__global__ __launch_bounds__(256) void trit_kernel(
    const float* __restrict__ qin, const float* __restrict__ k1,
    const float* __restrict__ k2, const float* __restrict__ v1,
    const float* __restrict__ v2, float* __restrict__ out) {
    extern __shared__ float sm[];
    int b = blockIdx.x;
    int tid = threadIdx.x;

    if (b < Z2_BASE) {
        // ==================== Z1: flash-style U / Cc / lk =====================
        // smem: k2s f4[272] @0 | k1s f4[272] @1088 | svc f4[256] @2176
        //       E @3200 (272) | Ccs @3472 (16) | mEs @3488 (16)
        float4* k2s = reinterpret_cast<float4*>(sm);
        float4* k1s = reinterpret_cast<float4*>(sm + 1088);
        float4* svc = reinterpret_cast<float4*>(sm + 2176);
        float*  E   = sm + 3200;
        float*  Ccs = sm + 3472;
        float*  mEs = sm + 3488;
        int tt = b % 12, n = b / 12;
        int t0 = tt * 16;
        int ty = tid >> 4, tx = tid & 15;
        const float* k1h = k1 + n * S * HD;
        const float* k2h = k2 + n * S * HD;
        const float* v1h = v1 + n * S * HD;

        k2s[ty * 17 + tx] = reinterpret_cast<const float4*>(k2h + (t0 + ty) * HD)[tx];
        if (tid < 16) { Ccs[tid] = 0.f; mEs[tid] = 0.f; }
        float4 Uacc = make_float4(0.f, 0.f, 0.f, 0.f);

        for (int s0 = 0; s0 <= t0; s0 += 16) {
            __syncthreads();
            k1s[ty * 17 + tx] = reinterpret_cast<const float4*>(k1h + (s0 + ty) * HD)[tx];
            {
                float4 x = reinterpret_cast<const float4*>(v1h + (s0 + ty) * HD)[tx];
                x.x = x.x / (1.f + __expf(-x.x));
                x.y = x.y / (1.f + __expf(-x.y));
                x.z = x.z / (1.f + __expf(-x.z));
                x.w = x.w / (1.f + __expf(-x.w));
                svc[ty * 16 + tx] = x;
            }
            __syncthreads();
            // E tile 16x16
            float c0 = 0.f, c1 = 0.f, c2 = 0.f, c3 = 0.f;
#pragma unroll
            for (int k4 = 0; k4 < 16; k4++) {
                float4 p = k1s[ty * 17 + k4];
                float4 r = k2s[tx * 17 + k4];
                c0 += p.x * r.x; c1 += p.y * r.y;
                c2 += p.z * r.z; c3 += p.w * r.w;
            }
            float acc = (c0 + c1) + (c2 + c3);
            int s_ = s0 + ty, t_ = t0 + tx;
            E[ty * 17 + tx] = (s_ <= t_) ? __expf(0.125f * acc) : 0.f;
            __syncthreads();
            // stats
            if (tid < 16) {
                float c = 0.f, m = 0.f;
#pragma unroll
                for (int s = 0; s < 16; s++) {
                    float e = E[s * 17 + tid];
                    c += e;
                    m = fmaxf(m, e);
                }
                Ccs[tid] += c;
                mEs[tid] = fmaxf(mEs[tid], m);
            }
            // U accumulate: thread (ty=t-local, tx=h-quad)
#pragma unroll
            for (int s = 0; s < 16; s++) {
                float e = E[s * 17 + ty];
                float4 v = svc[s * 16 + tx];
                Uacc.x += e * v.x; Uacc.y += e * v.y;
                Uacc.z += e * v.z; Uacc.w += e * v.w;
            }
        }
        __syncthreads();
        {
            float4 vv = reinterpret_cast<const float4*>(v2 + (n * S + t0 + ty) * HD)[tx];
            Uacc.x *= vv.x; Uacc.y *= vv.y; Uacc.z *= vv.z; Uacc.w *= vv.w;
            reinterpret_cast<float4*>(g_U)[(n * S + t0 + ty) * 16 + tx] = Uacc;
        }
        if (tid < 16) {
            g_Cc[n * S + t0 + tid] = Ccs[tid];
            g_lk[n * S + t0 + tid] = __logf(mEs[tid]);
        }
        // publish
        __threadfence();
        __syncthreads();
        if (tid == 0) atomicAdd(&d_done[n], 1);
    } else if (b < VG_BASE) {
        // ==================== Z2: softmax + z + M ============================
        float*  Qt  = sm;                                     // [t*17+ql] 3264
        float4* ks  = reinterpret_cast<float4*>(sm + 3264);
        float4* qs  = reinterpret_cast<float4*>(sm + 4352);
        float*  Ccs = sm + 5440;
        float*  lks = sm + 5632;
        float*  mqs = sm + 5824;
        float*  Dqs = sm + 5840;
        int idx = b - Z2_BASE;
        int qt = idx % 12, n = idx / 12;
        int q0 = qt * 16, T = q0 + 16;
        int ty = tid >> 4, tx = tid & 15;

        // acquire z1 results for this head
        if (tid == 0) {
            while (atomicAdd(&d_done[n], 0) < 12) __nanosleep(200);
            __threadfence();
        }
        __syncthreads();

        qs[ty * 17 + tx] = reinterpret_cast<const float4*>(qin + (n * S + q0 + ty) * HD)[tx];
        for (int i = tid; i < T; i += 256) {
            Ccs[i] = g_Cc[n * S + i];
            lks[i] = g_lk[n * S + i];
        }
        for (int t0 = 0; t0 < T; t0 += 16) {
            __syncthreads();
            ks[ty * 17 + tx] = reinterpret_cast<const float4*>(k2 + (n * S + t0 + ty) * HD)[tx];
            __syncthreads();
            float c0 = 0.f, c1 = 0.f, c2 = 0.f, c3 = 0.f;
#pragma unroll
            for (int k4 = 0; k4 < 16; k4++) {
                float4 p = ks[ty * 17 + k4];
                float4 r = qs[tx * 17 + k4];
                c0 += p.x * r.x; c1 += p.y * r.y;
                c2 += p.z * r.z; c3 += p.w * r.w;
            }
            Qt[(t0 + ty) * 17 + tx] = (c0 + c1) + (c2 + c3);
        }
        __syncthreads();
        // mq
        {
            int ql = ty, part = tx;
            int q = q0 + ql;
            float m = -INFINITY;
            for (int t = part; t < T; t += 16)
                if (t <= q) m = fmaxf(m, 0.125f * Qt[t * 17 + ql] + lks[t]);
#pragma unroll
            for (int off = 8; off; off >>= 1)
                m = fmaxf(m, __shfl_xor_sync(0xffffffffu, m, off));
            if (part == 0) mqs[ql] = m;
        }
        __syncthreads();
        // A in place
        for (int i2 = tid; i2 < T * 16; i2 += 256) {
            int t = i2 >> 4, ql = i2 & 15;
            float v = Qt[t * 17 + ql];
            Qt[t * 17 + ql] = (t <= q0 + ql) ? __expf(0.125f * v - mqs[ql]) : 0.f;
        }
        __syncthreads();
        // D + M
        {
            int ql = ty, part = tx;
            float d = 0.f;
            for (int t = part; t < T; t += 16) d += Qt[t * 17 + ql] * Ccs[t];
#pragma unroll
            for (int off = 8; off; off >>= 1)
                d += __shfl_xor_sync(0xffffffffu, d, off);
            if (part == 0) {
                Dqs[ql] = d;
                out[M_OFF + n * S + q0 + ql] = mqs[ql] + logf(d + 0.01f);
            }
        }
        __syncthreads();
        // z
        {
            int ql = ty, hq = tx;
            const float4* Ug = reinterpret_cast<const float4*>(g_U) + (n * S) * 16 + hq;
            float4 a0 = make_float4(0,0,0,0), a1 = a0, a2 = a0, a3 = a0;
            for (int t = 0; t < T; t += 4) {
                float w0 = Qt[t * 17 + ql];
                float w1 = Qt[(t + 1) * 17 + ql];
                float w2 = Qt[(t + 2) * 17 + ql];
                float w3 = Qt[(t + 3) * 17 + ql];
                float4 u0 = Ug[t * 16];
                float4 u1 = Ug[(t + 1) * 16];
                float4 u2 = Ug[(t + 2) * 16];
                float4 u3 = Ug[(t + 3) * 16];
                a0.x += w0 * u0.x; a0.y += w0 * u0.y; a0.z += w0 * u0.z; a0.w += w0 * u0.w;
                a1.x += w1 * u1.x; a1.y += w1 * u1.y; a1.z += w1 * u1.z; a1.w += w1 * u1.w;
                a2.x += w2 * u2.x; a2.y += w2 * u2.y; a2.z += w2 * u2.z; a2.w += w2 * u2.w;
                a3.x += w3 * u3.x; a3.y += w3 * u3.y; a3.z += w3 * u3.z; a3.w += w3 * u3.w;
            }
            float inv = 1.0f / Dqs[ql];
            float4 acc;
            acc.x = ((a0.x + a1.x) + (a2.x + a3.x)) * inv;
            acc.y = ((a0.y + a1.y) + (a2.y + a3.y)) * inv;
            acc.z = ((a0.z + a1.z) + (a2.z + a3.z)) * inv;
            acc.w = ((a0.w + a1.w) + (a2.w + a3.w)) * inv;
            reinterpret_cast<float4*>(out + Z_OFF)[(n * S + q0 + ql) * 16 + hq] = acc;
        }
        // consume + self-reset counters (graph-replay safe)
        __syncthreads();
        if (tid == 0) {
            int c = atomicAdd(&d_cons[n], 1);
            if (c == 11) { d_cons[n] = 0; d_done[n] = 0; __threadfence(); }
        }
    } else if (b < SC_BASE) {
        // ==================== vgated writer (silu inline) ====================
        float4* sv = reinterpret_cast<float4*>(sm);        // 256 f4
        float4* vv = reinterpret_cast<float4*>(sm) + 256;  // 256 f4
        int idx = b - VG_BASE;
        int tc = idx % 12;
        int r2 = idx / 12;
        int sc = r2 % 12, n = r2 / 12;
        int s0 = sc * 16, t0 = tc * 16;
        int ry = tid >> 4, rx = tid & 15;
        {
            float4 x = reinterpret_cast<const float4*>(v1 + (n * S + s0 + ry) * HD)[rx];
            x.x = x.x / (1.f + __expf(-x.x));
            x.y = x.y / (1.f + __expf(-x.y));
            x.z = x.z / (1.f + __expf(-x.z));
            x.w = x.w / (1.f + __expf(-x.w));
            sv[tid] = x;
        }
        vv[tid] = reinterpret_cast<const float4*>(v2 + (n * S + t0 + ry) * HD)[rx];
        __syncthreads();
        float4 b4 = vv[ry * 16 + rx];   // ry = t-local, rx = h4
        float4* dst = reinterpret_cast<float4*>(out + VG_OFF)
                      + ((unsigned)(n * S + s0) * S + t0 + ry) * 16 + rx;
#pragma unroll
        for (int sl = 0; sl < 16; sl++) {
            float4 a4 = sv[sl * 16 + rx];
            float4 o;
            o.x = a4.x * b4.x;
            o.y = a4.y * b4.y;
            o.z = a4.z * b4.z;
            o.w = a4.w * b4.w;
            __stcs(dst + sl * (S * 16), o);
        }
    } else {
        // ==================== score writer (self-contained qk/kk) ============
        // smem: k2row f4[16] @0 | qks @64 (192) | kks @256 (48)
        float4* k2r4 = reinterpret_cast<float4*>(sm);
        float*  qks  = sm + 64;
        float*  kks  = sm + 256;
        int idx = b - SC_BASE;
        int t = idx % S;
        int r2 = idx / S;
        int sc = r2 & 3, n = r2 >> 2;
        int s0 = sc * 48;
        if (tid < 16)
            k2r4[tid] = reinterpret_cast<const float4*>(k2 + (n * S + t) * HD)[tid];
        __syncthreads();
        if (tid < 192) {
            const float4* qrow = reinterpret_cast<const float4*>(qin + (n * S + tid) * HD);
            float c0 = 0.f, c1 = 0.f, c2 = 0.f, c3 = 0.f;
#pragma unroll
            for (int i = 0; i < 16; i += 4) {
                float4 a0 = k2r4[i],     b0 = qrow[i];
                float4 a1 = k2r4[i + 1], b1 = qrow[i + 1];
                float4 a2 = k2r4[i + 2], b2 = qrow[i + 2];
                float4 a3 = k2r4[i + 3], b3 = qrow[i + 3];
                c0 += a0.x*b0.x + a0.y*b0.y + a0.z*b0.z + a0.w*b0.w;
                c1 += a1.x*b1.x + a1.y*b1.y + a1.z*b1.z + a1.w*b1.w;
                c2 += a2.x*b2.x + a2.y*b2.y + a2.z*b2.z + a2.w*b2.w;
                c3 += a3.x*b3.x + a3.y*b3.y + a3.z*b3.z + a3.w*b3.w;
            }
            qks[tid] = (c0 + c1) + (c2 + c3);
        } else if (tid < 240) {
            int i2 = tid - 192;
            const float4* krow = reinterpret_cast<const float4*>(k1 + (n * S + s0 + i2) * HD);
            float c0 = 0.f, c1 = 0.f, c2 = 0.f, c3 = 0.f;
#pragma unroll
            for (int i = 0; i < 16; i += 4) {
                float4 a0 = k2r4[i],     b0 = krow[i];
                float4 a1 = k2r4[i + 1], b1 = krow[i + 1];
                float4 a2 = k2r4[i + 2], b2 = krow[i + 2];
                float4 a3 = k2r4[i + 3], b3 = krow[i + 3];
                c0 += a0.x*b0.x + a0.y*b0.y + a0.z*b0.z + a0.w*b0.w;
                c1 += a1.x*b1.x + a1.y*b1.y + a1.z*b1.z + a1.w*b1.w;
                c2 += a2.x*b2.x + a2.y*b2.y + a2.z*b2.z + a2.w*b2.w;
                c3 += a3.x*b3.x + a3.y*b3.y + a3.z*b3.z + a3.w*b3.w;
            }
            kks[i2] = (c0 + c1) + (c2 + c3);
        }
        __syncthreads();
        int ty = tid >> 4, tx = tid & 15;
        const float4* qks4 = reinterpret_cast<const float4*>(qks);
#pragma unroll
        for (int sl = 0; sl < 3; sl++) {
            int s = s0 + sl * 16 + ty;
            float kkv = kks[sl * 16 + ty];
            bool rowmask = (s > t);
            float4* dst = reinterpret_cast<float4*>(out + SCORE_OFF)
                          + ((unsigned)(n * S + s) * S + t) * 48;
#pragma unroll
            for (int c = 0; c < 3; c++) {
                int q4 = tx + 16 * c;
                float4 qv = qks4[q4];
                int q0 = q4 * 4;
                float4 o;
                o.x = (rowmask || t > q0)     ? -1000000.0f : kkv + qv.x;
                o.y = (rowmask || t > q0 + 1) ? -1000000.0f : kkv + qv.y;
                o.z = (rowmask || t > q0 + 2) ? -1000000.0f : kkv + qv.z;
                o.w = (rowmask || t > q0 + 3) ? -1000000.0f : kkv + qv.w;
                __stcs(dst + q4, o);
            }
        }
    }
}

extern "C" void kernel_launch(void* const* d_in, const int* in_sizes, int n_in,
                              void* d_out, int out_size) {
    const float* q  = (const float*)d_in[0];
    const float* k1 = (const float*)d_in[1];
    const float* k2 = (const float*)d_in[2];
    const float* v1 = (const float*)d_in[3];
    const float* v2 = (const float*)d_in[4];
    float* out = (float*)d_out;

    cudaFuncSetAttribute(trit_kernel, cudaFuncAttributeMaxDynamicSharedMemorySize,
                         SMEM_FLOATS * sizeof(float));

    trit_kernel<<<TOTAL_BLOCKS, 256, SMEM_FLOATS * sizeof(float)>>>(
        q, k1, k2, v1, v2, out);
}

// round 12
// speedup vs baseline: 1.4753x; 1.4753x over previous
#include <cuda_runtime.h>
#include <math.h>

#define S 192
#define HD 64
#define NHEAD 8
#define SS (S*S)

// Output layout (concatenated flattened tuple, reference return order):
#define Z_OFF      0u
#define SCORE_OFF  98304u
#define VG_OFF     56721408u
#define M_OFF      75595776u

// scratch
__device__ float g_qk[NHEAD * SS];      // [n][t][q] (A.gemm -> B.score)
__device__ float g_kk[NHEAD * SS];      // [n][s][t] (A.gemm -> B.score)
__device__ float g_U[NHEAD * S * HD];   // (B.z1 -> B.z2)
__device__ float g_Cc[NHEAD * S];
__device__ float g_lk[NHEAD * S];
__device__ int   d_done[NHEAD];         // self-resetting
__device__ int   d_cons[NHEAD];

// ====================== KERNEL A: gemms only ================================
#define A_SMEM_FLOATS 4352

__global__ __launch_bounds__(256) void megaA(
    const float* __restrict__ qin, const float* __restrict__ k1,
    const float* __restrict__ k2) {
    extern __shared__ float sm[];
    float4* As4 = reinterpret_cast<float4*>(sm);          // 544 f4
    float4* Bs4 = reinterpret_cast<float4*>(sm) + 544;    // 544 f4
    int tid = threadIdx.x;
    int ty = tid >> 4, tx = tid & 15;
    int idx = blockIdx.x;
    const float *Ain, *Bin;
    float* Cout;
    if (idx < 288) { Ain = k2; Bin = qin; Cout = g_qk; }
    else { idx -= 288; Ain = k1; Bin = k2; Cout = g_kk; }
    int j0 = (idx % 6) * 32, i0 = ((idx / 6) % 6) * 32, n = idx / 36;
    const float* Ah = Ain + (n * S + i0) * HD;
    const float* Bh = Bin + (n * S + j0) * HD;
#pragma unroll
    for (int k = 0; k < 2; k++) {
        int l = tid + k * 256;
        int r = l >> 4, c4 = l & 15;
        As4[r * 17 + c4] = reinterpret_cast<const float4*>(Ah + r * HD)[c4];
        Bs4[r * 17 + c4] = reinterpret_cast<const float4*>(Bh + r * HD)[c4];
    }
    __syncthreads();
    float a00 = 0.f, a01 = 0.f, a10 = 0.f, a11 = 0.f;
#pragma unroll
    for (int k4 = 0; k4 < 16; k4++) {
        float4 p0 = As4[ty * 17 + k4];
        float4 p1 = As4[(ty + 16) * 17 + k4];
        float4 r0 = Bs4[tx * 17 + k4];
        float4 r1 = Bs4[(tx + 16) * 17 + k4];
        a00 += p0.x*r0.x + p0.y*r0.y + p0.z*r0.z + p0.w*r0.w;
        a01 += p0.x*r1.x + p0.y*r1.y + p0.z*r1.z + p0.w*r1.w;
        a10 += p1.x*r0.x + p1.y*r0.y + p1.z*r0.z + p1.w*r0.w;
        a11 += p1.x*r1.x + p1.y*r1.y + p1.z*r1.z + p1.w*r1.w;
    }
    float* Cr = Cout + n * SS;
    Cr[(i0 + ty) * S + j0 + tx]           = a00;
    Cr[(i0 + ty) * S + j0 + tx + 16]      = a01;
    Cr[(i0 + ty + 16) * S + j0 + tx]      = a10;
    Cr[(i0 + ty + 16) * S + j0 + tx + 16] = a11;
}

// ====================== KERNEL B: z1 + z2 + writers =========================
#define Z1_BASE    0
#define Z2_BASE    96
#define VG_BASE    192
#define SC_BASE    1344
#define VG_BLOCKS  1152   // 8 * 12 * 12
#define SC_BLOCKS  18432  // 8 * 12 * 192
#define B_BLOCKS   (SC_BASE + SC_BLOCKS)
#define B_SMEM_FLOATS 5856

__global__ __launch_bounds__(256) void megaB(
    const float* __restrict__ qin, const float* __restrict__ k1,
    const float* __restrict__ k2, const float* __restrict__ v1,
    const float* __restrict__ v2, float* __restrict__ out) {
    extern __shared__ float sm[];
    int b = blockIdx.x;
    int tid = threadIdx.x;

    if (b < Z2_BASE) {
        // ---------------- Z1: U / Cc / lk (raw inputs only) -----------------
        float4* k2s = reinterpret_cast<float4*>(sm);           // 272 f4
        float4* k1s = reinterpret_cast<float4*>(sm + 1088);    // 272 f4
        float4* svc = reinterpret_cast<float4*>(sm + 2176);    // 256 f4
        float*  E   = sm + 3200;                                // 272
        float*  Ccs = sm + 3472;                                // 16
        float*  mEs = sm + 3488;                                // 16
        int tt = b % 12, n = b / 12;
        int t0 = tt * 16;
        int ty = tid >> 4, tx = tid & 15;
        const float* k1h = k1 + n * S * HD;
        const float* k2h = k2 + n * S * HD;
        const float* v1h = v1 + n * S * HD;

        k2s[ty * 17 + tx] = reinterpret_cast<const float4*>(k2h + (t0 + ty) * HD)[tx];
        if (tid < 16) { Ccs[tid] = 0.f; mEs[tid] = 0.f; }
        float4 Uacc = make_float4(0.f, 0.f, 0.f, 0.f);

        for (int s0 = 0; s0 <= t0; s0 += 16) {
            __syncthreads();
            k1s[ty * 17 + tx] = reinterpret_cast<const float4*>(k1h + (s0 + ty) * HD)[tx];
            {
                float4 x = reinterpret_cast<const float4*>(v1h + (s0 + ty) * HD)[tx];
                x.x = x.x / (1.f + __expf(-x.x));
                x.y = x.y / (1.f + __expf(-x.y));
                x.z = x.z / (1.f + __expf(-x.z));
                x.w = x.w / (1.f + __expf(-x.w));
                svc[ty * 16 + tx] = x;
            }
            __syncthreads();
            float c0 = 0.f, c1 = 0.f, c2 = 0.f, c3 = 0.f;
#pragma unroll
            for (int k4 = 0; k4 < 16; k4++) {
                float4 p = k1s[ty * 17 + k4];
                float4 r = k2s[tx * 17 + k4];
                c0 += p.x * r.x; c1 += p.y * r.y;
                c2 += p.z * r.z; c3 += p.w * r.w;
            }
            float acc = (c0 + c1) + (c2 + c3);
            int s_ = s0 + ty, t_ = t0 + tx;
            E[ty * 17 + tx] = (s_ <= t_) ? __expf(0.125f * acc) : 0.f;
            __syncthreads();
            if (tid < 16) {
                float c = 0.f, m = 0.f;
#pragma unroll
                for (int s = 0; s < 16; s++) {
                    float e = E[s * 17 + tid];
                    c += e;
                    m = fmaxf(m, e);
                }
                Ccs[tid] += c;
                mEs[tid] = fmaxf(mEs[tid], m);
            }
#pragma unroll
            for (int s = 0; s < 16; s++) {
                float e = E[s * 17 + ty];
                float4 v = svc[s * 16 + tx];
                Uacc.x += e * v.x; Uacc.y += e * v.y;
                Uacc.z += e * v.z; Uacc.w += e * v.w;
            }
        }
        __syncthreads();
        {
            float4 vv = reinterpret_cast<const float4*>(v2 + (n * S + t0 + ty) * HD)[tx];
            Uacc.x *= vv.x; Uacc.y *= vv.y; Uacc.z *= vv.z; Uacc.w *= vv.w;
            reinterpret_cast<float4*>(g_U)[(n * S + t0 + ty) * 16 + tx] = Uacc;
        }
        if (tid < 16) {
            g_Cc[n * S + t0 + tid] = Ccs[tid];
            g_lk[n * S + t0 + tid] = __logf(mEs[tid]);
        }
        __threadfence();
        __syncthreads();
        if (tid == 0) atomicAdd(&d_done[n], 1);
    } else if (b < VG_BASE) {
        // ---------------- Z2: softmax + z + M --------------------------------
        float*  Qt  = sm;                                     // 3264
        float4* ks  = reinterpret_cast<float4*>(sm + 3264);
        float4* qs  = reinterpret_cast<float4*>(sm + 4352);
        float*  Ccs = sm + 5440;
        float*  lks = sm + 5632;
        float*  mqs = sm + 5824;
        float*  Dqs = sm + 5840;
        int idx = b - Z2_BASE;
        int qt = idx % 12, n = idx / 12;
        int q0 = qt * 16, T = q0 + 16;
        int ty = tid >> 4, tx = tid & 15;

        if (tid == 0) {
            while (atomicAdd(&d_done[n], 0) < 12) __nanosleep(200);
            __threadfence();
        }
        __syncthreads();

        qs[ty * 17 + tx] = reinterpret_cast<const float4*>(qin + (n * S + q0 + ty) * HD)[tx];
        for (int i = tid; i < T; i += 256) {
            Ccs[i] = g_Cc[n * S + i];
            lks[i] = g_lk[n * S + i];
        }
        for (int t0 = 0; t0 < T; t0 += 16) {
            __syncthreads();
            ks[ty * 17 + tx] = reinterpret_cast<const float4*>(k2 + (n * S + t0 + ty) * HD)[tx];
            __syncthreads();
            float c0 = 0.f, c1 = 0.f, c2 = 0.f, c3 = 0.f;
#pragma unroll
            for (int k4 = 0; k4 < 16; k4++) {
                float4 p = ks[ty * 17 + k4];
                float4 r = qs[tx * 17 + k4];
                c0 += p.x * r.x; c1 += p.y * r.y;
                c2 += p.z * r.z; c3 += p.w * r.w;
            }
            Qt[(t0 + ty) * 17 + tx] = (c0 + c1) + (c2 + c3);
        }
        __syncthreads();
        {
            int ql = ty, part = tx;
            int q = q0 + ql;
            float m = -INFINITY;
            for (int t = part; t < T; t += 16)
                if (t <= q) m = fmaxf(m, 0.125f * Qt[t * 17 + ql] + lks[t]);
#pragma unroll
            for (int off = 8; off; off >>= 1)
                m = fmaxf(m, __shfl_xor_sync(0xffffffffu, m, off));
            if (part == 0) mqs[ql] = m;
        }
        __syncthreads();
        for (int i2 = tid; i2 < T * 16; i2 += 256) {
            int t = i2 >> 4, ql = i2 & 15;
            float v = Qt[t * 17 + ql];
            Qt[t * 17 + ql] = (t <= q0 + ql) ? __expf(0.125f * v - mqs[ql]) : 0.f;
        }
        __syncthreads();
        {
            int ql = ty, part = tx;
            float d = 0.f;
            for (int t = part; t < T; t += 16) d += Qt[t * 17 + ql] * Ccs[t];
#pragma unroll
            for (int off = 8; off; off >>= 1)
                d += __shfl_xor_sync(0xffffffffu, d, off);
            if (part == 0) {
                Dqs[ql] = d;
                out[M_OFF + n * S + q0 + ql] = mqs[ql] + logf(d + 0.01f);
            }
        }
        __syncthreads();
        {
            int ql = ty, hq = tx;
            const float4* Ug = reinterpret_cast<const float4*>(g_U) + (n * S) * 16 + hq;
            float4 a0 = make_float4(0,0,0,0), a1 = a0, a2 = a0, a3 = a0;
            for (int t = 0; t < T; t += 4) {
                float w0 = Qt[t * 17 + ql];
                float w1 = Qt[(t + 1) * 17 + ql];
                float w2 = Qt[(t + 2) * 17 + ql];
                float w3 = Qt[(t + 3) * 17 + ql];
                float4 u0 = Ug[t * 16];
                float4 u1 = Ug[(t + 1) * 16];
                float4 u2 = Ug[(t + 2) * 16];
                float4 u3 = Ug[(t + 3) * 16];
                a0.x += w0 * u0.x; a0.y += w0 * u0.y; a0.z += w0 * u0.z; a0.w += w0 * u0.w;
                a1.x += w1 * u1.x; a1.y += w1 * u1.y; a1.z += w1 * u1.z; a1.w += w1 * u1.w;
                a2.x += w2 * u2.x; a2.y += w2 * u2.y; a2.z += w2 * u2.z; a2.w += w2 * u2.w;
                a3.x += w3 * u3.x; a3.y += w3 * u3.y; a3.z += w3 * u3.z; a3.w += w3 * u3.w;
            }
            float inv = 1.0f / Dqs[ql];
            float4 acc;
            acc.x = ((a0.x + a1.x) + (a2.x + a3.x)) * inv;
            acc.y = ((a0.y + a1.y) + (a2.y + a3.y)) * inv;
            acc.z = ((a0.z + a1.z) + (a2.z + a3.z)) * inv;
            acc.w = ((a0.w + a1.w) + (a2.w + a3.w)) * inv;
            reinterpret_cast<float4*>(out + Z_OFF)[(n * S + q0 + ql) * 16 + hq] = acc;
        }
        __syncthreads();
        if (tid == 0) {
            int c = atomicAdd(&d_cons[n], 1);
            if (c == 11) { d_cons[n] = 0; d_done[n] = 0; __threadfence(); }
        }
    } else if (b < SC_BASE) {
        // ---------------- vgated writer (silu inline) -----------------------
        float4* sv = reinterpret_cast<float4*>(sm);        // 256 f4
        float4* vv = reinterpret_cast<float4*>(sm) + 256;  // 256 f4
        int idx = b - VG_BASE;
        int tc = idx % 12;
        int r2 = idx / 12;
        int sc = r2 % 12, n = r2 / 12;
        int s0 = sc * 16, t0 = tc * 16;
        int ry = tid >> 4, rx = tid & 15;
        {
            float4 x = reinterpret_cast<const float4*>(v1 + (n * S + s0 + ry) * HD)[rx];
            x.x = x.x / (1.f + __expf(-x.x));
            x.y = x.y / (1.f + __expf(-x.y));
            x.z = x.z / (1.f + __expf(-x.z));
            x.w = x.w / (1.f + __expf(-x.w));
            sv[tid] = x;
        }
        vv[tid] = reinterpret_cast<const float4*>(v2 + (n * S + t0 + ry) * HD)[rx];
        __syncthreads();
        float4 b4 = vv[ry * 16 + rx];   // ry = t-local, rx = h4
        float4* dst = reinterpret_cast<float4*>(out + VG_OFF)
                      + ((unsigned)(n * S + s0) * S + t0 + ry) * 16 + rx;
#pragma unroll
        for (int sl = 0; sl < 16; sl++) {
            float4 a4 = sv[sl * 16 + rx];
            float4 o;
            o.x = a4.x * b4.x;
            o.y = a4.y * b4.y;
            o.z = a4.z * b4.z;
            o.w = a4.w * b4.w;
            dst[sl * (S * 16)] = o;
        }
    } else {
        // ---------------- score row writer (reads g_qk/g_kk) ----------------
        float* qks = sm;        // 192
        float* kks = sm + 192;  // 16
        int idx = b - SC_BASE;
        int t = idx % S;
        int r2 = idx / S;
        int sc = r2 % 12, n = r2 / 12;
        int s0 = sc * 16;
        if (tid < 48)
            reinterpret_cast<float4*>(qks)[tid] =
                reinterpret_cast<const float4*>(g_qk)[(unsigned)(n * S + t) * 48 + tid];
        if (tid >= 64 && tid < 80)
            kks[tid - 64] = g_kk[(unsigned)(n * S + s0 + tid - 64) * S + t];
        __syncthreads();
        int ty = tid >> 4, tx = tid & 15;
        int s = s0 + ty;
        float kkv = kks[ty];
        bool rowmask = (s > t);
        float4* dst = reinterpret_cast<float4*>(out + SCORE_OFF)
                      + ((unsigned)(n * S + s) * S + t) * 48;
#pragma unroll
        for (int c = 0; c < 3; c++) {
            int q4 = tx + 16 * c;
            float4 qv = reinterpret_cast<float4*>(qks)[q4];
            int q0 = q4 * 4;
            float4 o;
            o.x = (rowmask || t > q0)     ? -1000000.0f : kkv + qv.x;
            o.y = (rowmask || t > q0 + 1) ? -1000000.0f : kkv + qv.y;
            o.z = (rowmask || t > q0 + 2) ? -1000000.0f : kkv + qv.z;
            o.w = (rowmask || t > q0 + 3) ? -1000000.0f : kkv + qv.w;
            dst[q4] = o;
        }
    }
}

extern "C" void kernel_launch(void* const* d_in, const int* in_sizes, int n_in,
                              void* d_out, int out_size) {
    const float* q  = (const float*)d_in[0];
    const float* k1 = (const float*)d_in[1];
    const float* k2 = (const float*)d_in[2];
    const float* v1 = (const float*)d_in[3];
    const float* v2 = (const float*)d_in[4];
    float* out = (float*)d_out;

    cudaFuncSetAttribute(megaA, cudaFuncAttributeMaxDynamicSharedMemorySize,
                         A_SMEM_FLOATS * sizeof(float));
    cudaFuncSetAttribute(megaB, cudaFuncAttributeMaxDynamicSharedMemorySize,
                         B_SMEM_FLOATS * sizeof(float));

    // A: qk/kk gemms only (~4 us)
    megaA<<<576, 256, A_SMEM_FLOATS * sizeof(float)>>>(q, k1, k2);

    // B: z1 (raw inputs) + z2 (spin on z1) + vgated (inline silu) + score
    megaB<<<B_BLOCKS, 256, B_SMEM_FLOATS * sizeof(float)>>>(
        q, k1, k2, v1, v2, out);
}